// round 15
// baseline (speedup 1.0000x reference)
#include <cuda_runtime.h>
#include <cuda_fp16.h>
#include <cstdint>

#define DIMN   1024
#define BSZ    4
#define LSEQ   8192
#define MROWS  (BSZ * LSEQ)          // 32768
#define GATE_ELEMS ((size_t)MROWS * DIMN)

#define NCHUNK 128
#define TCH    64                    // NCHUNK * TCH == LSEQ
#define DH     (DIMN / 2)            // half2 channels per row

// ---------------- GEMM tiling (legacy mma.sync fp16, fp32 accum) ------------
#define BK       64                  // k-chunk (halves) per stage
#define NKCH     (DIMN / BK)         // 16
#define NSTAGE   3
#define ASTR     72                  // halves per A/B smem row (64 + 8 pad -> 144B)
#define A_ST_HL  (128 * ASTR)        // 9216 halves / stage
#define B_ST_HL  (128 * ASTR)        // 9216 halves / stage
#define STG_HL   (A_ST_HL + B_ST_HL) // 18432 halves = 36864 B
#define DYN_SMEM (NSTAGE * STG_HL * 2)   // 110592 B

// ---------------- scratch (device globals: allocation-free) ----------------
__device__ __half g_z[(size_t)4 * MROWS * DIMN];   // ACTIVATED gates fp16: F, I, G, O
__device__ __half g_X16[(size_t)MROWS * DIMN];     // X rounded to fp16 (RNE)
__device__ __half g_W16[(size_t)4 * DIMN * DIMN];  // W^T per gate: [n][k] fp16
__device__ float  g_Ac[BSZ * NCHUNK * DIMN];
__device__ float  g_Bc[BSZ * NCHUNK * DIMN];
__device__ float  g_h0[BSZ * NCHUNK * DIMN];

// ---------------- helpers ----------------
__device__ __forceinline__ float sigm(float x) { return 1.0f / (1.0f + __expf(-x)); }
__device__ __forceinline__ float tanh_acc(float x) {
    x = fminf(fmaxf(x, -15.0f), 15.0f);
    float e = __expf(2.0f * x);
    return (e - 1.0f) / (e + 1.0f);
}
__device__ __forceinline__ uint32_t smem_u32(const void* p) {
    uint32_t a;
    asm("{ .reg .u64 t; cvta.to.shared.u64 t, %1; cvt.u32.u64 %0, t; }" : "=r"(a) : "l"(p));
    return a;
}
__device__ __forceinline__ void cp16(uint32_t dst, const void* src) {
    asm volatile("cp.async.cg.shared.global [%0], [%1], 16;" :: "r"(dst), "l"(src));
}
__device__ __forceinline__ void cp_commit() { asm volatile("cp.async.commit_group;" ::: "memory"); }
template <int N> __device__ __forceinline__ void cp_wait() {
    asm volatile("cp.async.wait_group %0;" :: "n"(N) : "memory");
}
__device__ __forceinline__ void mma_f16(float c[4], const unsigned a[4], const unsigned b[2]) {
    asm volatile(
        "mma.sync.aligned.m16n8k16.row.col.f32.f16.f16.f32 "
        "{%0,%1,%2,%3}, {%4,%5,%6,%7}, {%8,%9}, {%0,%1,%2,%3};\n"
        : "+f"(c[0]), "+f"(c[1]), "+f"(c[2]), "+f"(c[3])
        : "r"(a[0]), "r"(a[1]), "r"(a[2]), "r"(a[3]), "r"(b[0]), "r"(b[1]));
}

// ---------------- prepass: round X to fp16 (RNE) ----------------------------
__global__ void prep_x(const float4* __restrict__ X) {
    size_t i = (size_t)blockIdx.x * 256 + threadIdx.x;
    float4 v = X[i];
    __half2* out = (__half2*)(g_X16 + 4 * i);
    out[0] = __floats2half2_rn(v.x, v.y);
    out[1] = __floats2half2_rn(v.z, v.w);
}

// ---------------- prepass: W^T [n][k] with fp16 rounding --------------------
__global__ void prep_w(const float* __restrict__ W0, const float* __restrict__ W1,
                       const float* __restrict__ W2, const float* __restrict__ W3) {
    __shared__ float t[32][33];
    const int g = blockIdx.z;
    const float* W = (g == 0) ? W0 : (g == 1) ? W1 : (g == 2) ? W2 : W3;
    __half* Wt = g_W16 + (size_t)g * DIMN * DIMN;
    const int n0 = blockIdx.x * 32, k0 = blockIdx.y * 32;
    const int tx = threadIdx.x, ty = threadIdx.y;   // 32 x 8
    #pragma unroll
    for (int r = 0; r < 4; r++)
        t[ty + r * 8][tx] = W[(size_t)(k0 + ty + r * 8) * DIMN + n0 + tx];
    __syncthreads();
    #pragma unroll
    for (int r = 0; r < 4; r++)
        Wt[(size_t)(n0 + ty + r * 8) * DIMN + k0 + tx] = __float2half_rn(t[tx][ty + r * 8]);
}

// ---------------- GEMM + fused activation epilogue (fp16 gate store) --------
// grid (32, 256): x = gate(&3) + ntile(>>2)*4 [A mtile hot in L2], y = mtile.
// 256 threads = 8 warps (2 M x 4 N), warp tile 64x32.
// fp16 mma m16n8k16, 3-stage cp.async, BK=64 (one barrier per 64 MMAs), occ 2.
__global__ void __launch_bounds__(256, 2) gemm_gates(
    const float* __restrict__ b0, const float* __restrict__ b1,
    const float* __restrict__ b2, const float* __restrict__ b3)
{
    extern __shared__ __half smem[];

    const int tid  = threadIdx.x;
    const int lane = tid & 31;
    const int wid  = tid >> 5;
    const int wm   = (wid >> 2) * 64;   // warp M offset
    const int wn   = (wid & 3) * 32;    // warp N offset
    const int gr   = lane >> 2;         // 0..7
    const int tg   = lane & 3;          // 0..3

    const int g  = blockIdx.x & 3;
    const int nb = blockIdx.x >> 2;
    const int gn = nb * 128;
    const size_t gm = (size_t)blockIdx.y * 128;

    const float* bias = (g == 0) ? b0 : (g == 1) ? b1 : (g == 2) ? b2 : b3;
    const __half* A = g_X16;                                 // [32768,1024]
    const __half* B = g_W16 + (size_t)g * DIMN * DIMN;       // [1024(n),1024(k)]
    __half* Z = g_z + (size_t)g * GATE_ELEMS;

    const uint32_t sb = smem_u32(smem);

    float acc[4][4][4];
    #pragma unroll
    for (int mt = 0; mt < 4; mt++)
        #pragma unroll
        for (int nt = 0; nt < 4; nt++)
            #pragma unroll
            for (int j = 0; j < 4; j++) acc[mt][nt][j] = 0.0f;

    // producer: stage slot <- k-chunk kc (kc in units of BK halves)
    auto load_stage = [&](int slot, int kc) {
        const uint32_t aB = sb + (uint32_t)(slot * STG_HL) * 2u;
        const uint32_t bB = aB + (uint32_t)A_ST_HL * 2u;
        const int k0 = kc * BK;
        // A: 128 rows x 8 segs of 16B (8 halves) -> 1024 chunks, 4/thread
        #pragma unroll
        for (int i = 0; i < 4; i++) {
            int ch = i * 256 + tid;
            int row = ch >> 3, seg = ch & 7;
            cp16(aB + (uint32_t)(row * ASTR + seg * 8) * 2u,
                 A + (gm + row) * DIMN + k0 + seg * 8);
        }
        // B: 128 n-rows x 8 segs of 16B -> 1024 chunks, 4/thread
        #pragma unroll
        for (int i = 0; i < 4; i++) {
            int ch = i * 256 + tid;
            int row = ch >> 3, seg = ch & 7;
            cp16(bB + (uint32_t)(row * ASTR + seg * 8) * 2u,
                 B + (size_t)(gn + row) * DIMN + k0 + seg * 8);
        }
    };

    load_stage(0, 0); cp_commit();
    load_stage(1, 1); cp_commit();

    int slot = 0;
    for (int kc = 0; kc < NKCH; kc++) {
        cp_wait<NSTAGE - 2>();           // current stage landed
        __syncthreads();                 // all warps done reading the slot we refill

        if (kc + 2 < NKCH) {
            int ns = slot + 2; if (ns >= NSTAGE) ns -= NSTAGE;
            load_stage(ns, kc + 2);
        }
        cp_commit();

        const __half* As = smem + slot * STG_HL;
        const __half* Bs = As + A_ST_HL;

        #pragma unroll
        for (int kk = 0; kk < 4; kk++) {
            const int kb = kk * 16;      // k16 per mma
            unsigned af[4][4], bf[4][2];
            #pragma unroll
            for (int mt = 0; mt < 4; mt++) {
                int r = wm + mt * 16 + gr;
                af[mt][0] = *(const unsigned*)&As[r * ASTR + kb + 2 * tg];
                af[mt][1] = *(const unsigned*)&As[(r + 8) * ASTR + kb + 2 * tg];
                af[mt][2] = *(const unsigned*)&As[r * ASTR + kb + 2 * tg + 8];
                af[mt][3] = *(const unsigned*)&As[(r + 8) * ASTR + kb + 2 * tg + 8];
            }
            #pragma unroll
            for (int nt = 0; nt < 4; nt++) {
                int n = wn + nt * 8 + gr;
                bf[nt][0] = *(const unsigned*)&Bs[n * ASTR + kb + 2 * tg];
                bf[nt][1] = *(const unsigned*)&Bs[n * ASTR + kb + 2 * tg + 8];
            }
            #pragma unroll
            for (int mt = 0; mt < 4; mt++)
                #pragma unroll
                for (int nt = 0; nt < 4; nt++)
                    mma_f16(acc[mt][nt], af[mt], bf[nt]);
        }
        slot++; if (slot >= NSTAGE) slot = 0;
    }

    // epilogue: bias + activation, store ACTIVATED gate as fp16
    #pragma unroll
    for (int mt = 0; mt < 4; mt++) {
        #pragma unroll
        for (int nt = 0; nt < 4; nt++) {
            int r = wm + mt * 16 + gr;
            int n = gn + wn + nt * 8 + 2 * tg;
            float bv0 = __ldg(bias + n);
            float bv1 = __ldg(bias + n + 1);
            float z00 = acc[mt][nt][0] + bv0, z01 = acc[mt][nt][1] + bv1;
            float z10 = acc[mt][nt][2] + bv0, z11 = acc[mt][nt][3] + bv1;
            float2 v0, v1;
            if (g == 1) {
                v0.x = tanh_acc(z00); v0.y = tanh_acc(z01);
                v1.x = tanh_acc(z10); v1.y = tanh_acc(z11);
            } else {
                v0.x = sigm(z00); v0.y = sigm(z01);
                v1.x = sigm(z10); v1.y = sigm(z11);
            }
            *(__half2*)(Z + (gm + r) * (size_t)DIMN + n)     = __floats2half2_rn(v0.x, v0.y);
            *(__half2*)(Z + (gm + r + 8) * (size_t)DIMN + n) = __floats2half2_rn(v1.x, v1.y);
        }
    }
}

// ---------------- scan pass 1: per-chunk (A = prod F, B = local tail) -------
// 2 channels per thread via half2; math in fp32.
__global__ void scan_reduce()
{
    const int d2 = blockIdx.x * 256 + threadIdx.x;     // 0..511
    const int c  = blockIdx.y;
    const int b  = blockIdx.z;
    const size_t base2 = (size_t)(b * LSEQ + c * TCH) * DH + d2;
    const __half2* F = (const __half2*)g_z + base2;
    const __half2* I = (const __half2*)(g_z + GATE_ELEMS) + base2;
    const __half2* G = (const __half2*)(g_z + 2 * GATE_ELEMS) + base2;

    float2 a = make_float2(1.0f, 1.0f);
    float2 bb = make_float2(0.0f, 0.0f);
    #pragma unroll 4
    for (int t = 0; t < TCH; t++) {
        float2 f  = __half22float2(F[t * DH]);
        float2 iv2 = __half22float2(I[t * DH]);
        float2 gv = __half22float2(G[t * DH]);
        a.x *= f.x; a.y *= f.y;
        bb.x = fmaf(f.x, bb.x, iv2.x * gv.x);
        bb.y = fmaf(f.y, bb.y, iv2.y * gv.y);
    }
    int o2 = (b * NCHUNK + c) * DH + d2;
    ((float2*)g_Ac)[o2] = a;
    ((float2*)g_Bc)[o2] = bb;
}

// ---------------- scan pass 2: sequential combine over chunks ---------------
__global__ void scan_combine(const float* __restrict__ hinit)
{
    const int b = blockIdx.x;
    const int d = threadIdx.x;
    float h = hinit[d];
    for (int c = 0; c < NCHUNK; c++) {
        int o = (b * NCHUNK + c) * DIMN + d;
        g_h0[o] = h;
        h = fmaf(g_Ac[o], h, g_Bc[o]);
    }
}

// ---------------- scan pass 3: apply with carry-in, write y (fp32) ----------
__global__ void scan_apply(float* __restrict__ Y)
{
    const int d2 = blockIdx.x * 256 + threadIdx.x;     // 0..511
    const int c  = blockIdx.y;
    const int b  = blockIdx.z;
    const size_t base2 = (size_t)(b * LSEQ + c * TCH) * DH + d2;
    const __half2* F = (const __half2*)g_z + base2;
    const __half2* I = (const __half2*)(g_z + GATE_ELEMS) + base2;
    const __half2* G = (const __half2*)(g_z + 2 * GATE_ELEMS) + base2;
    const __half2* O = (const __half2*)(g_z + 3 * GATE_ELEMS) + base2;

    float2 h = ((const float2*)g_h0)[(b * NCHUNK + c) * DH + d2];
    float2* Yo = (float2*)Y + base2;
    #pragma unroll 4
    for (int t = 0; t < TCH; t++) {
        float2 f  = __half22float2(F[t * DH]);
        float2 iv = __half22float2(I[t * DH]);
        float2 gv = __half22float2(G[t * DH]);
        float2 ov = __half22float2(O[t * DH]);
        h.x = fmaf(f.x, h.x, iv.x * gv.x);
        h.y = fmaf(f.y, h.y, iv.y * gv.y);
        float2 o;
        o.x = tanh_acc(h.x) * ov.x;
        o.y = tanh_acc(h.y) * ov.y;
        Yo[t * DH] = o;
    }
}

// ---------------- launch ----------------------------------------------------
extern "C" void kernel_launch(void* const* d_in, const int* in_sizes, int n_in,
                              void* d_out, int out_size)
{
    (void)in_sizes; (void)n_in; (void)out_size;
    const float* x   = (const float*)d_in[0];
    const float* Wf  = (const float*)d_in[1];
    const float* bf  = (const float*)d_in[2];
    const float* Wi  = (const float*)d_in[3];
    const float* bi  = (const float*)d_in[4];
    const float* Wig = (const float*)d_in[5];
    const float* big = (const float*)d_in[6];
    const float* Wog = (const float*)d_in[7];
    const float* bog = (const float*)d_in[8];
    const float* h0  = (const float*)d_in[9];
    float* y = (float*)d_out;

    static bool attr_done = false;
    if (!attr_done) {
        cudaFuncSetAttribute(gemm_gates, cudaFuncAttributeMaxDynamicSharedMemorySize, DYN_SMEM);
        attr_done = true;
    }

    prep_x<<<(MROWS * DIMN / 4) / 256, 256>>>((const float4*)x);
    prep_w<<<dim3(32, 32, 4), dim3(32, 8)>>>(Wf, Wi, Wig, Wog);
    gemm_gates<<<dim3(32, 256), 256, DYN_SMEM>>>(bf, bi, big, bog);
    scan_reduce<<<dim3(DH / 256, NCHUNK, BSZ), 256>>>();
    scan_combine<<<BSZ, DIMN>>>(h0);
    scan_apply<<<dim3(DH / 256, NCHUNK, BSZ), 256>>>(y);
}

// round 16
// speedup vs baseline: 1.5224x; 1.5224x over previous
#include <cuda_runtime.h>
#include <cuda_fp16.h>
#include <cstdint>

#define DIMN   1024
#define BSZ    4
#define LSEQ   8192
#define MROWS  (BSZ * LSEQ)          // 32768
#define GATE_ELEMS ((size_t)MROWS * DIMN)

#define NCHUNK 128
#define TCH    64                    // NCHUNK * TCH == LSEQ
#define DH     (DIMN / 2)            // half2 channels per row

// ---------------- GEMM tiling (legacy mma.sync fp16, fp32 accum) ------------
#define BK       64                  // k-chunk (halves) per stage
#define NKCH     (DIMN / BK)         // 16
#define NSTAGE   3
#define ASTR     72                  // halves per A/B smem row (64 + 8 pad -> 144B)
#define A_ST_HL  (128 * ASTR)        // 9216 halves / stage
#define B_ST_HL  (128 * ASTR)        // 9216 halves / stage
#define STG_HL   (A_ST_HL + B_ST_HL) // 18432 halves = 36864 B
#define DYN_SMEM (NSTAGE * STG_HL * 2)   // 110592 B
#define TSTR     136                 // epilogue tile stride in halves (128 + 8 pad)

// ---------------- scratch (device globals: allocation-free) ----------------
__device__ __half g_z[(size_t)4 * MROWS * DIMN];   // ACTIVATED gates fp16: F, I, G, O
__device__ __half g_X16[(size_t)MROWS * DIMN];     // X rounded to fp16 (RNE)
__device__ __half g_W16[(size_t)4 * DIMN * DIMN];  // W^T per gate: [n][k] fp16
__device__ float  g_Ac[BSZ * NCHUNK * DIMN];
__device__ float  g_Bc[BSZ * NCHUNK * DIMN];
__device__ float  g_h0[BSZ * NCHUNK * DIMN];

// ---------------- helpers ----------------
__device__ __forceinline__ float sigm(float x) { return 1.0f / (1.0f + __expf(-x)); }
__device__ __forceinline__ float tanh_acc(float x) {
    x = fminf(fmaxf(x, -15.0f), 15.0f);
    float e = __expf(2.0f * x);
    return (e - 1.0f) / (e + 1.0f);
}
__device__ __forceinline__ uint32_t smem_u32(const void* p) {
    uint32_t a;
    asm("{ .reg .u64 t; cvta.to.shared.u64 t, %1; cvt.u32.u64 %0, t; }" : "=r"(a) : "l"(p));
    return a;
}
__device__ __forceinline__ void cp16(uint32_t dst, const void* src) {
    asm volatile("cp.async.cg.shared.global [%0], [%1], 16;" :: "r"(dst), "l"(src));
}
__device__ __forceinline__ void cp_commit() { asm volatile("cp.async.commit_group;" ::: "memory"); }
template <int N> __device__ __forceinline__ void cp_wait() {
    asm volatile("cp.async.wait_group %0;" :: "n"(N) : "memory");
}
__device__ __forceinline__ void mma_f16(float c[4], const unsigned a[4], const unsigned b[2]) {
    asm volatile(
        "mma.sync.aligned.m16n8k16.row.col.f32.f16.f16.f32 "
        "{%0,%1,%2,%3}, {%4,%5,%6,%7}, {%8,%9}, {%0,%1,%2,%3};\n"
        : "+f"(c[0]), "+f"(c[1]), "+f"(c[2]), "+f"(c[3])
        : "r"(a[0]), "r"(a[1]), "r"(a[2]), "r"(a[3]), "r"(b[0]), "r"(b[1]));
}

// ---------------- prepass: round X to fp16 (RNE) ----------------------------
__global__ void prep_x(const float4* __restrict__ X) {
    size_t i = (size_t)blockIdx.x * 256 + threadIdx.x;
    float4 v = X[i];
    __half2* out = (__half2*)(g_X16 + 4 * i);
    out[0] = __floats2half2_rn(v.x, v.y);
    out[1] = __floats2half2_rn(v.z, v.w);
}

// ---------------- prepass: W^T [n][k] with fp16 rounding --------------------
__global__ void prep_w(const float* __restrict__ W0, const float* __restrict__ W1,
                       const float* __restrict__ W2, const float* __restrict__ W3) {
    __shared__ float t[32][33];
    const int g = blockIdx.z;
    const float* W = (g == 0) ? W0 : (g == 1) ? W1 : (g == 2) ? W2 : W3;
    __half* Wt = g_W16 + (size_t)g * DIMN * DIMN;
    const int n0 = blockIdx.x * 32, k0 = blockIdx.y * 32;
    const int tx = threadIdx.x, ty = threadIdx.y;   // 32 x 8
    #pragma unroll
    for (int r = 0; r < 4; r++)
        t[ty + r * 8][tx] = W[(size_t)(k0 + ty + r * 8) * DIMN + n0 + tx];
    __syncthreads();
    #pragma unroll
    for (int r = 0; r < 4; r++)
        Wt[(size_t)(n0 + ty + r * 8) * DIMN + k0 + tx] = __float2half_rn(t[tx][ty + r * 8]);
}

// ---------------- GEMM + fused activation epilogue (fp16, smem-staged) ------
// grid (32, 256): x = gate(&3) + ntile(>>2)*4 [A mtile hot in L2], y = mtile.
// 256 threads = 8 warps (2 M x 4 N), warp tile 64x32.
// fp16 mma m16n8k16, 3-stage cp.async, BK=64, occ 2.
// Epilogue stages the 128x128 fp16 tile in smem, then writes full 16B lines
// (full 32B sectors -> no partial-sector write-allocate).
__global__ void __launch_bounds__(256, 2) gemm_gates(
    const float* __restrict__ b0, const float* __restrict__ b1,
    const float* __restrict__ b2, const float* __restrict__ b3)
{
    extern __shared__ __half smem[];

    const int tid  = threadIdx.x;
    const int lane = tid & 31;
    const int wid  = tid >> 5;
    const int wm   = (wid >> 2) * 64;   // warp M offset
    const int wn   = (wid & 3) * 32;    // warp N offset
    const int gr   = lane >> 2;         // 0..7
    const int tg   = lane & 3;          // 0..3

    const int g  = blockIdx.x & 3;
    const int nb = blockIdx.x >> 2;
    const int gn = nb * 128;
    const size_t gm = (size_t)blockIdx.y * 128;

    const float* bias = (g == 0) ? b0 : (g == 1) ? b1 : (g == 2) ? b2 : b3;
    const __half* A = g_X16;                                 // [32768,1024]
    const __half* B = g_W16 + (size_t)g * DIMN * DIMN;       // [1024(n),1024(k)]
    __half* Z = g_z + (size_t)g * GATE_ELEMS;

    const uint32_t sb = smem_u32(smem);

    float acc[4][4][4];
    #pragma unroll
    for (int mt = 0; mt < 4; mt++)
        #pragma unroll
        for (int nt = 0; nt < 4; nt++)
            #pragma unroll
            for (int j = 0; j < 4; j++) acc[mt][nt][j] = 0.0f;

    // producer: stage slot <- k-chunk kc (kc in units of BK halves)
    auto load_stage = [&](int slot, int kc) {
        const uint32_t aB = sb + (uint32_t)(slot * STG_HL) * 2u;
        const uint32_t bB = aB + (uint32_t)A_ST_HL * 2u;
        const int k0 = kc * BK;
        // A: 128 rows x 8 segs of 16B (8 halves) -> 1024 chunks, 4/thread
        #pragma unroll
        for (int i = 0; i < 4; i++) {
            int ch = i * 256 + tid;
            int row = ch >> 3, seg = ch & 7;
            cp16(aB + (uint32_t)(row * ASTR + seg * 8) * 2u,
                 A + (gm + row) * DIMN + k0 + seg * 8);
        }
        // B: 128 n-rows x 8 segs of 16B -> 1024 chunks, 4/thread
        #pragma unroll
        for (int i = 0; i < 4; i++) {
            int ch = i * 256 + tid;
            int row = ch >> 3, seg = ch & 7;
            cp16(bB + (uint32_t)(row * ASTR + seg * 8) * 2u,
                 B + (size_t)(gn + row) * DIMN + k0 + seg * 8);
        }
    };

    load_stage(0, 0); cp_commit();
    load_stage(1, 1); cp_commit();

    int slot = 0;
    for (int kc = 0; kc < NKCH; kc++) {
        cp_wait<NSTAGE - 2>();           // current stage landed
        __syncthreads();                 // all warps done reading the slot we refill

        if (kc + 2 < NKCH) {
            int ns = slot + 2; if (ns >= NSTAGE) ns -= NSTAGE;
            load_stage(ns, kc + 2);
        }
        cp_commit();

        const __half* As = smem + slot * STG_HL;
        const __half* Bs = As + A_ST_HL;

        #pragma unroll
        for (int kk = 0; kk < 4; kk++) {
            const int kb = kk * 16;      // k16 per mma
            unsigned af[4][4], bf[4][2];
            #pragma unroll
            for (int mt = 0; mt < 4; mt++) {
                int r = wm + mt * 16 + gr;
                af[mt][0] = *(const unsigned*)&As[r * ASTR + kb + 2 * tg];
                af[mt][1] = *(const unsigned*)&As[(r + 8) * ASTR + kb + 2 * tg];
                af[mt][2] = *(const unsigned*)&As[r * ASTR + kb + 2 * tg + 8];
                af[mt][3] = *(const unsigned*)&As[(r + 8) * ASTR + kb + 2 * tg + 8];
            }
            #pragma unroll
            for (int nt = 0; nt < 4; nt++) {
                int n = wn + nt * 8 + gr;
                bf[nt][0] = *(const unsigned*)&Bs[n * ASTR + kb + 2 * tg];
                bf[nt][1] = *(const unsigned*)&Bs[n * ASTR + kb + 2 * tg + 8];
            }
            #pragma unroll
            for (int mt = 0; mt < 4; mt++)
                #pragma unroll
                for (int nt = 0; nt < 4; nt++)
                    mma_f16(acc[mt][nt], af[mt], bf[nt]);
        }
        slot++; if (slot >= NSTAGE) slot = 0;
    }

    // ---- epilogue: bias + activation -> smem tile -> coalesced 16B stores ----
    cp_wait<0>();
    __syncthreads();                     // pipeline smem now reusable as tile

    #pragma unroll
    for (int mt = 0; mt < 4; mt++) {
        #pragma unroll
        for (int nt = 0; nt < 4; nt++) {
            int r = wm + mt * 16 + gr;
            int n = wn + nt * 8 + 2 * tg;          // block-local col
            float bv0 = __ldg(bias + gn + n);
            float bv1 = __ldg(bias + gn + n + 1);
            float z00 = acc[mt][nt][0] + bv0, z01 = acc[mt][nt][1] + bv1;
            float z10 = acc[mt][nt][2] + bv0, z11 = acc[mt][nt][3] + bv1;
            float2 v0, v1;
            if (g == 1) {
                v0.x = tanh_acc(z00); v0.y = tanh_acc(z01);
                v1.x = tanh_acc(z10); v1.y = tanh_acc(z11);
            } else {
                v0.x = sigm(z00); v0.y = sigm(z01);
                v1.x = sigm(z10); v1.y = sigm(z11);
            }
            *(__half2*)&smem[r * TSTR + n]       = __floats2half2_rn(v0.x, v0.y);
            *(__half2*)&smem[(r + 8) * TSTR + n] = __floats2half2_rn(v1.x, v1.y);
        }
    }
    __syncthreads();

    // stream tile out: 128 rows x 256B, 16B per thread-store, fully coalesced
    #pragma unroll
    for (int i = 0; i < 8; i++) {
        int idx = i * 256 + tid;
        int row = idx >> 4, seg = idx & 15;
        uint4 v = *(const uint4*)&smem[row * TSTR + seg * 8];
        *(uint4*)(Z + (gm + row) * (size_t)DIMN + gn + seg * 8) = v;
    }
}

// ---------------- scan pass 1: per-chunk (A = prod F, B = local tail) -------
// 2 channels per thread via half2; math in fp32.
__global__ void scan_reduce()
{
    const int d2 = blockIdx.x * 256 + threadIdx.x;     // 0..511
    const int c  = blockIdx.y;
    const int b  = blockIdx.z;
    const size_t base2 = (size_t)(b * LSEQ + c * TCH) * DH + d2;
    const __half2* F = (const __half2*)g_z + base2;
    const __half2* I = (const __half2*)(g_z + GATE_ELEMS) + base2;
    const __half2* G = (const __half2*)(g_z + 2 * GATE_ELEMS) + base2;

    float2 a = make_float2(1.0f, 1.0f);
    float2 bb = make_float2(0.0f, 0.0f);
    #pragma unroll 4
    for (int t = 0; t < TCH; t++) {
        float2 f  = __half22float2(F[t * DH]);
        float2 iv2 = __half22float2(I[t * DH]);
        float2 gv = __half22float2(G[t * DH]);
        a.x *= f.x; a.y *= f.y;
        bb.x = fmaf(f.x, bb.x, iv2.x * gv.x);
        bb.y = fmaf(f.y, bb.y, iv2.y * gv.y);
    }
    int o2 = (b * NCHUNK + c) * DH + d2;
    ((float2*)g_Ac)[o2] = a;
    ((float2*)g_Bc)[o2] = bb;
}

// ---------------- scan pass 2: sequential combine over chunks ---------------
__global__ void scan_combine(const float* __restrict__ hinit)
{
    const int b = blockIdx.x;
    const int d = threadIdx.x;
    float h = hinit[d];
    for (int c = 0; c < NCHUNK; c++) {
        int o = (b * NCHUNK + c) * DIMN + d;
        g_h0[o] = h;
        h = fmaf(g_Ac[o], h, g_Bc[o]);
    }
}

// ---------------- scan pass 3: apply with carry-in, write y (fp32) ----------
__global__ void scan_apply(float* __restrict__ Y)
{
    const int d2 = blockIdx.x * 256 + threadIdx.x;     // 0..511
    const int c  = blockIdx.y;
    const int b  = blockIdx.z;
    const size_t base2 = (size_t)(b * LSEQ + c * TCH) * DH + d2;
    const __half2* F = (const __half2*)g_z + base2;
    const __half2* I = (const __half2*)(g_z + GATE_ELEMS) + base2;
    const __half2* G = (const __half2*)(g_z + 2 * GATE_ELEMS) + base2;
    const __half2* O = (const __half2*)(g_z + 3 * GATE_ELEMS) + base2;

    float2 h = ((const float2*)g_h0)[(b * NCHUNK + c) * DH + d2];
    float2* Yo = (float2*)Y + base2;
    #pragma unroll 4
    for (int t = 0; t < TCH; t++) {
        float2 f  = __half22float2(F[t * DH]);
        float2 iv = __half22float2(I[t * DH]);
        float2 gv = __half22float2(G[t * DH]);
        float2 ov = __half22float2(O[t * DH]);
        h.x = fmaf(f.x, h.x, iv.x * gv.x);
        h.y = fmaf(f.y, h.y, iv.y * gv.y);
        float2 o;
        o.x = tanh_acc(h.x) * ov.x;
        o.y = tanh_acc(h.y) * ov.y;
        Yo[t * DH] = o;
    }
}

// ---------------- launch ----------------------------------------------------
extern "C" void kernel_launch(void* const* d_in, const int* in_sizes, int n_in,
                              void* d_out, int out_size)
{
    (void)in_sizes; (void)n_in; (void)out_size;
    const float* x   = (const float*)d_in[0];
    const float* Wf  = (const float*)d_in[1];
    const float* bf  = (const float*)d_in[2];
    const float* Wi  = (const float*)d_in[3];
    const float* bi  = (const float*)d_in[4];
    const float* Wig = (const float*)d_in[5];
    const float* big = (const float*)d_in[6];
    const float* Wog = (const float*)d_in[7];
    const float* bog = (const float*)d_in[8];
    const float* h0  = (const float*)d_in[9];
    float* y = (float*)d_out;

    static bool attr_done = false;
    if (!attr_done) {
        cudaFuncSetAttribute(gemm_gates, cudaFuncAttributeMaxDynamicSharedMemorySize, DYN_SMEM);
        attr_done = true;
    }

    prep_x<<<(MROWS * DIMN / 4) / 256, 256>>>((const float4*)x);
    prep_w<<<dim3(32, 32, 4), dim3(32, 8)>>>(Wf, Wi, Wig, Wog);
    gemm_gates<<<dim3(32, 256), 256, DYN_SMEM>>>(bf, bi, big, bog);
    scan_reduce<<<dim3(DH / 256, NCHUNK, BSZ), 256>>>();
    scan_combine<<<BSZ, DIMN>>>(h0);
    scan_apply<<<dim3(DH / 256, NCHUNK, BSZ), 256>>>(y);
}

// round 17
// speedup vs baseline: 1.6120x; 1.0589x over previous
#include <cuda_runtime.h>
#include <cuda_fp16.h>
#include <cstdint>

#define DIMN   1024
#define BSZ    4
#define LSEQ   8192
#define MROWS  (BSZ * LSEQ)          // 32768
#define GATE_ELEMS ((size_t)MROWS * DIMN)

#define NCHUNK 128
#define TCH    64                    // NCHUNK * TCH == LSEQ
#define DH     (DIMN / 2)            // half2 channels per row

// ---------------- GEMM tiling (legacy mma.sync fp16, fp32 accum) ------------
#define BK       64                  // k-chunk (halves) per stage
#define NKCH     (DIMN / BK)         // 16
#define NSTAGE   3
#define ASTR     72                  // halves per A/B smem row (64 + 8 pad -> 144B)
#define A_ST_HL  (128 * ASTR)        // 9216 halves / stage
#define B_ST_HL  (128 * ASTR)        // 9216 halves / stage
#define STG_HL   (A_ST_HL + B_ST_HL) // 18432 halves = 36864 B
#define DYN_SMEM (NSTAGE * STG_HL * 2)   // 110592 B
#define TSTR     136                 // epilogue tile stride in halves (128 + 8 pad)

// ---------------- scratch (device globals: allocation-free) ----------------
__device__ __half g_z[(size_t)4 * MROWS * DIMN];   // ACTIVATED gates fp16: F, I, G, O
__device__ __half g_X16[(size_t)MROWS * DIMN];     // X rounded to fp16 (RNE)
__device__ __half g_W16[(size_t)4 * DIMN * DIMN];  // W^T per gate: [n][k] fp16
__device__ float  g_Ac[BSZ * NCHUNK * DIMN];
__device__ float  g_Bc[BSZ * NCHUNK * DIMN];
__device__ float  g_h0[BSZ * NCHUNK * DIMN];

// ---------------- helpers ----------------
__device__ __forceinline__ float sigm(float x) { return 1.0f / (1.0f + __expf(-x)); }
__device__ __forceinline__ float tanh_acc(float x) {
    x = fminf(fmaxf(x, -15.0f), 15.0f);
    float e = __expf(2.0f * x);
    return (e - 1.0f) / (e + 1.0f);
}
__device__ __forceinline__ uint32_t smem_u32(const void* p) {
    uint32_t a;
    asm("{ .reg .u64 t; cvta.to.shared.u64 t, %1; cvt.u32.u64 %0, t; }" : "=r"(a) : "l"(p));
    return a;
}
__device__ __forceinline__ void cp16(uint32_t dst, const void* src) {
    asm volatile("cp.async.cg.shared.global [%0], [%1], 16;" :: "r"(dst), "l"(src));
}
__device__ __forceinline__ void cp_commit() { asm volatile("cp.async.commit_group;" ::: "memory"); }
template <int N> __device__ __forceinline__ void cp_wait() {
    asm volatile("cp.async.wait_group %0;" :: "n"(N) : "memory");
}
__device__ __forceinline__ void mma_f16(float c[4], const unsigned a[4], const unsigned b[2]) {
    asm volatile(
        "mma.sync.aligned.m16n8k16.row.col.f32.f16.f16.f32 "
        "{%0,%1,%2,%3}, {%4,%5,%6,%7}, {%8,%9}, {%0,%1,%2,%3};\n"
        : "+f"(c[0]), "+f"(c[1]), "+f"(c[2]), "+f"(c[3])
        : "r"(a[0]), "r"(a[1]), "r"(a[2]), "r"(a[3]), "r"(b[0]), "r"(b[1]));
}
__device__ __forceinline__ void ldsm_x4(unsigned& r0, unsigned& r1, unsigned& r2, unsigned& r3,
                                        uint32_t addr) {
    asm volatile("ldmatrix.sync.aligned.m8n8.x4.shared.b16 {%0,%1,%2,%3}, [%4];"
                 : "=r"(r0), "=r"(r1), "=r"(r2), "=r"(r3) : "r"(addr));
}

// ---------------- prepass: round X to fp16 (RNE) ----------------------------
__global__ void prep_x(const float4* __restrict__ X) {
    size_t i = (size_t)blockIdx.x * 256 + threadIdx.x;
    float4 v = X[i];
    __half2* out = (__half2*)(g_X16 + 4 * i);
    out[0] = __floats2half2_rn(v.x, v.y);
    out[1] = __floats2half2_rn(v.z, v.w);
}

// ---------------- prepass: W^T [n][k] with fp16 rounding --------------------
__global__ void prep_w(const float* __restrict__ W0, const float* __restrict__ W1,
                       const float* __restrict__ W2, const float* __restrict__ W3) {
    __shared__ float t[32][33];
    const int g = blockIdx.z;
    const float* W = (g == 0) ? W0 : (g == 1) ? W1 : (g == 2) ? W2 : W3;
    __half* Wt = g_W16 + (size_t)g * DIMN * DIMN;
    const int n0 = blockIdx.x * 32, k0 = blockIdx.y * 32;
    const int tx = threadIdx.x, ty = threadIdx.y;   // 32 x 8
    #pragma unroll
    for (int r = 0; r < 4; r++)
        t[ty + r * 8][tx] = W[(size_t)(k0 + ty + r * 8) * DIMN + n0 + tx];
    __syncthreads();
    #pragma unroll
    for (int r = 0; r < 4; r++)
        Wt[(size_t)(n0 + ty + r * 8) * DIMN + k0 + tx] = __float2half_rn(t[tx][ty + r * 8]);
}

// ---------------- GEMM + fused activation epilogue (fp16, smem-staged) ------
// grid (32, 256): x = gate(&3) + ntile(>>2)*4 [A mtile hot in L2], y = mtile.
// 256 threads = 8 warps (2 M x 4 N), warp tile 64x32.
// fp16 mma m16n8k16, ldmatrix fragment loads, 3-stage cp.async, BK=64, occ 2.
__global__ void __launch_bounds__(256, 2) gemm_gates(
    const float* __restrict__ b0, const float* __restrict__ b1,
    const float* __restrict__ b2, const float* __restrict__ b3)
{
    extern __shared__ __half smem[];

    const int tid  = threadIdx.x;
    const int lane = tid & 31;
    const int wid  = tid >> 5;
    const int wm   = (wid >> 2) * 64;   // warp M offset
    const int wn   = (wid & 3) * 32;    // warp N offset
    const int gr   = lane >> 2;         // 0..7
    const int tg   = lane & 3;          // 0..3

    // ldmatrix lane->row/col mapping (see fragment layout of mma.m16n8k16)
    const int alr  = ((lane >> 3) & 1) * 8 + (lane & 7);  // A row within 16
    const int acol = (lane >> 4) * 8;                     // A col: 0 or 8
    const int blr  = (lane >> 4) * 8 + (lane & 7);        // B n-row within 16
    const int bcol = ((lane >> 3) & 1) * 8;               // B col: 0 or 8

    const int g  = blockIdx.x & 3;
    const int nb = blockIdx.x >> 2;
    const int gn = nb * 128;
    const size_t gm = (size_t)blockIdx.y * 128;

    const float* bias = (g == 0) ? b0 : (g == 1) ? b1 : (g == 2) ? b2 : b3;
    const __half* A = g_X16;                                 // [32768,1024]
    const __half* B = g_W16 + (size_t)g * DIMN * DIMN;       // [1024(n),1024(k)]
    __half* Z = g_z + (size_t)g * GATE_ELEMS;

    const uint32_t sb = smem_u32(smem);

    float acc[4][4][4];
    #pragma unroll
    for (int mt = 0; mt < 4; mt++)
        #pragma unroll
        for (int nt = 0; nt < 4; nt++)
            #pragma unroll
            for (int j = 0; j < 4; j++) acc[mt][nt][j] = 0.0f;

    // producer: stage slot <- k-chunk kc (kc in units of BK halves)
    auto load_stage = [&](int slot, int kc) {
        const uint32_t aB = sb + (uint32_t)(slot * STG_HL) * 2u;
        const uint32_t bB = aB + (uint32_t)A_ST_HL * 2u;
        const int k0 = kc * BK;
        #pragma unroll
        for (int i = 0; i < 4; i++) {
            int ch = i * 256 + tid;
            int row = ch >> 3, seg = ch & 7;
            cp16(aB + (uint32_t)(row * ASTR + seg * 8) * 2u,
                 A + (gm + row) * DIMN + k0 + seg * 8);
        }
        #pragma unroll
        for (int i = 0; i < 4; i++) {
            int ch = i * 256 + tid;
            int row = ch >> 3, seg = ch & 7;
            cp16(bB + (uint32_t)(row * ASTR + seg * 8) * 2u,
                 B + (size_t)(gn + row) * DIMN + k0 + seg * 8);
        }
    };

    load_stage(0, 0); cp_commit();
    load_stage(1, 1); cp_commit();

    int slot = 0;
    for (int kc = 0; kc < NKCH; kc++) {
        cp_wait<NSTAGE - 2>();           // current stage landed
        __syncthreads();                 // all warps done reading the slot we refill

        if (kc + 2 < NKCH) {
            int ns = slot + 2; if (ns >= NSTAGE) ns -= NSTAGE;
            load_stage(ns, kc + 2);
        }
        cp_commit();

        const uint32_t aS = sb + (uint32_t)(slot * STG_HL) * 2u;
        const uint32_t bS = aS + (uint32_t)A_ST_HL * 2u;

        #pragma unroll
        for (int kk = 0; kk < 4; kk++) {
            const int kb = kk * 16;      // k16 per mma
            unsigned af[4][4], bf[4][2];
            #pragma unroll
            for (int mt = 0; mt < 4; mt++) {
                uint32_t addr = aS + (uint32_t)((wm + mt * 16 + alr) * ASTR + kb + acol) * 2u;
                ldsm_x4(af[mt][0], af[mt][1], af[mt][2], af[mt][3], addr);
            }
            #pragma unroll
            for (int np = 0; np < 2; np++) {   // pairs of n-tiles
                uint32_t addr = bS + (uint32_t)((wn + np * 16 + blr) * ASTR + kb + bcol) * 2u;
                ldsm_x4(bf[2 * np][0], bf[2 * np][1], bf[2 * np + 1][0], bf[2 * np + 1][1], addr);
            }
            #pragma unroll
            for (int mt = 0; mt < 4; mt++)
                #pragma unroll
                for (int nt = 0; nt < 4; nt++)
                    mma_f16(acc[mt][nt], af[mt], bf[nt]);
        }
        slot++; if (slot >= NSTAGE) slot = 0;
    }

    // ---- epilogue: bias + activation -> smem tile -> coalesced 16B stores ----
    cp_wait<0>();
    __syncthreads();                     // pipeline smem now reusable as tile

    #pragma unroll
    for (int mt = 0; mt < 4; mt++) {
        #pragma unroll
        for (int nt = 0; nt < 4; nt++) {
            int r = wm + mt * 16 + gr;
            int n = wn + nt * 8 + 2 * tg;          // block-local col
            float bv0 = __ldg(bias + gn + n);
            float bv1 = __ldg(bias + gn + n + 1);
            float z00 = acc[mt][nt][0] + bv0, z01 = acc[mt][nt][1] + bv1;
            float z10 = acc[mt][nt][2] + bv0, z11 = acc[mt][nt][3] + bv1;
            float2 v0, v1;
            if (g == 1) {
                v0.x = tanh_acc(z00); v0.y = tanh_acc(z01);
                v1.x = tanh_acc(z10); v1.y = tanh_acc(z11);
            } else {
                v0.x = sigm(z00); v0.y = sigm(z01);
                v1.x = sigm(z10); v1.y = sigm(z11);
            }
            *(__half2*)&smem[r * TSTR + n]       = __floats2half2_rn(v0.x, v0.y);
            *(__half2*)&smem[(r + 8) * TSTR + n] = __floats2half2_rn(v1.x, v1.y);
        }
    }
    __syncthreads();

    // stream tile out: 128 rows x 256B, 16B per thread-store, fully coalesced
    #pragma unroll
    for (int i = 0; i < 8; i++) {
        int idx = i * 256 + tid;
        int row = idx >> 4, seg = idx & 15;
        uint4 v = *(const uint4*)&smem[row * TSTR + seg * 8];
        *(uint4*)(Z + (gm + row) * (size_t)DIMN + gn + seg * 8) = v;
    }
}

// ---------------- scan pass 1: per-chunk (A = prod F, B = local tail) -------
__global__ void scan_reduce()
{
    const int d2 = blockIdx.x * 256 + threadIdx.x;     // 0..511
    const int c  = blockIdx.y;
    const int b  = blockIdx.z;
    const size_t base2 = (size_t)(b * LSEQ + c * TCH) * DH + d2;
    const __half2* F = (const __half2*)g_z + base2;
    const __half2* I = (const __half2*)(g_z + GATE_ELEMS) + base2;
    const __half2* G = (const __half2*)(g_z + 2 * GATE_ELEMS) + base2;

    float2 a = make_float2(1.0f, 1.0f);
    float2 bb = make_float2(0.0f, 0.0f);
    #pragma unroll 4
    for (int t = 0; t < TCH; t++) {
        float2 f  = __half22float2(F[t * DH]);
        float2 iv2 = __half22float2(I[t * DH]);
        float2 gv = __half22float2(G[t * DH]);
        a.x *= f.x; a.y *= f.y;
        bb.x = fmaf(f.x, bb.x, iv2.x * gv.x);
        bb.y = fmaf(f.y, bb.y, iv2.y * gv.y);
    }
    int o2 = (b * NCHUNK + c) * DH + d2;
    ((float2*)g_Ac)[o2] = a;
    ((float2*)g_Bc)[o2] = bb;
}

// ---------------- scan pass 2: sequential combine over chunks ---------------
__global__ void scan_combine(const float* __restrict__ hinit)
{
    const int b = blockIdx.x;
    const int d = threadIdx.x;
    float h = hinit[d];
    for (int c = 0; c < NCHUNK; c++) {
        int o = (b * NCHUNK + c) * DIMN + d;
        g_h0[o] = h;
        h = fmaf(g_Ac[o], h, g_Bc[o]);
    }
}

// ---------------- scan pass 3: apply with carry-in, write y (fp32) ----------
__global__ void scan_apply(float* __restrict__ Y)
{
    const int d2 = blockIdx.x * 256 + threadIdx.x;     // 0..511
    const int c  = blockIdx.y;
    const int b  = blockIdx.z;
    const size_t base2 = (size_t)(b * LSEQ + c * TCH) * DH + d2;
    const __half2* F = (const __half2*)g_z + base2;
    const __half2* I = (const __half2*)(g_z + GATE_ELEMS) + base2;
    const __half2* G = (const __half2*)(g_z + 2 * GATE_ELEMS) + base2;
    const __half2* O = (const __half2*)(g_z + 3 * GATE_ELEMS) + base2;

    float2 h = ((const float2*)g_h0)[(b * NCHUNK + c) * DH + d2];
    float2* Yo = (float2*)Y + base2;
    #pragma unroll 4
    for (int t = 0; t < TCH; t++) {
        float2 f  = __half22float2(F[t * DH]);
        float2 iv = __half22float2(I[t * DH]);
        float2 gv = __half22float2(G[t * DH]);
        float2 ov = __half22float2(O[t * DH]);
        h.x = fmaf(f.x, h.x, iv.x * gv.x);
        h.y = fmaf(f.y, h.y, iv.y * gv.y);
        float2 o;
        o.x = tanh_acc(h.x) * ov.x;
        o.y = tanh_acc(h.y) * ov.y;
        Yo[t * DH] = o;
    }
}

// ---------------- launch ----------------------------------------------------
extern "C" void kernel_launch(void* const* d_in, const int* in_sizes, int n_in,
                              void* d_out, int out_size)
{
    (void)in_sizes; (void)n_in; (void)out_size;
    const float* x   = (const float*)d_in[0];
    const float* Wf  = (const float*)d_in[1];
    const float* bf  = (const float*)d_in[2];
    const float* Wi  = (const float*)d_in[3];
    const float* bi  = (const float*)d_in[4];
    const float* Wig = (const float*)d_in[5];
    const float* big = (const float*)d_in[6];
    const float* Wog = (const float*)d_in[7];
    const float* bog = (const float*)d_in[8];
    const float* h0  = (const float*)d_in[9];
    float* y = (float*)d_out;

    static bool attr_done = false;
    if (!attr_done) {
        cudaFuncSetAttribute(gemm_gates, cudaFuncAttributeMaxDynamicSharedMemorySize, DYN_SMEM);
        attr_done = true;
    }

    prep_x<<<(MROWS * DIMN / 4) / 256, 256>>>((const float4*)x);
    prep_w<<<dim3(32, 32, 4), dim3(32, 8)>>>(Wf, Wi, Wig, Wog);
    gemm_gates<<<dim3(32, 256), 256, DYN_SMEM>>>(bf, bi, big, bog);
    scan_reduce<<<dim3(DH / 256, NCHUNK, BSZ), 256>>>();
    scan_combine<<<BSZ, DIMN>>>(h0);
    scan_apply<<<dim3(DH / 256, NCHUNK, BSZ), 256>>>(y);
}